// round 6
// baseline (speedup 1.0000x reference)
#include <cuda_runtime.h>
#include <cuda_bf16.h>
#include <cstdint>
#include <math.h>

// ============================================================================
// EdgeModel via tf32 mma.sync (baseline PTX; tcgen05 not available at the
// harness's compute_103 target):
//   out[e] = softplus( concat(nf[src], nf[dst], ef[e], gf[batch[src]]) @ W.T ) - log2
// Single-pass tf32 (cvt.rna both operands), fp32 accumulate.
// R6: latency-hiding focus. CTA = 128 edges x 128 out, 128 threads (4 warps,
// warp tile 64x64), 3-stage cp.async pipeline, 2 CTAs/SM.
// K = 384 in 12 chunks of 32 fp32 (128B rows, SW128 swizzle).
// W pre-converted/pre-swizzled to a __device__ image once per launch.
// ============================================================================

#define H        128
#define DN       128
#define DE       64
#define DG       64
#define KC       32
#define NCH      12
#define TILE_E   128
#define THREADS  128
#define STAGES   3
#define LOG2F_CONST 0.6931471805599453f

#define SWZ128(off) ((off) ^ (((off) >> 3) & 0x70))

// per stage: A 128x128B = 16KB, W 128x128B = 16KB
#define STAGE_SZ 32768
#define SIDX     (STAGES * STAGE_SZ)
#define SMEM_TOTAL (SIDX + 3 * TILE_E * 4)    // 98304 + 1536

// W image: [12 chunks][128 n x 32 k fp32(tf32-rounded)], SW128-swizzled rows
__device__ uint32_t g_Wimg[NCH * 128 * KC];

__device__ __forceinline__ uint32_t f2tf32(float x) {
    uint32_t r; asm("cvt.rna.tf32.f32 %0, %1;" : "=r"(r) : "f"(x)); return r;
}

__global__ void w_convert_kernel(const float* __restrict__ W) {
    int i = blockIdx.x * 256 + threadIdx.x;     // over 128*384
    if (i >= H * 384) return;
    int n = i / 384;
    int k = i - n * 384;
    int c  = k >> 5;
    int kk = k & 31;
    uint32_t v = f2tf32(W[n * 384 + k]);
    unsigned char* img = (unsigned char*)g_Wimg + c * 16384;
    *(uint32_t*)(img + SWZ128((uint32_t)(n * 128 + kk * 4))) = v;
}

__device__ __forceinline__ uint32_t smem_u32(const void* p) {
    uint32_t a;
    asm("{ .reg .u64 t; cvta.to.shared.u64 t, %1; cvt.u32.u64 %0, t; }" : "=r"(a) : "l"(p));
    return a;
}
__device__ __forceinline__ void ldsm_x4(uint32_t* r, uint32_t addr) {
    asm volatile("ldmatrix.sync.aligned.m8n8.x4.shared.b16 {%0,%1,%2,%3}, [%4];"
                 : "=r"(r[0]), "=r"(r[1]), "=r"(r[2]), "=r"(r[3]) : "r"(addr));
}
__device__ __forceinline__ void cp_async16(uint32_t dst, const void* src) {
    asm volatile("cp.async.cg.shared.global [%0], [%1], 16;" :: "r"(dst), "l"(src));
}
__device__ __forceinline__ void mma_tf32(float* d, const uint32_t* a, uint32_t b0, uint32_t b1) {
    asm volatile(
        "mma.sync.aligned.m16n8k8.row.col.f32.tf32.tf32.f32 "
        "{%0,%1,%2,%3}, {%4,%5,%6,%7}, {%8,%9}, {%0,%1,%2,%3};"
        : "+f"(d[0]), "+f"(d[1]), "+f"(d[2]), "+f"(d[3])
        : "r"(a[0]), "r"(a[1]), "r"(a[2]), "r"(a[3]), "r"(b0), "r"(b1));
}
__device__ __forceinline__ float softplus_shift(float h) {
    return fmaxf(h, 0.0f) + __logf(1.0f + __expf(-fabsf(h))) - LOG2F_CONST;
}

__global__ __launch_bounds__(THREADS, 2)
void edge_tf32_kernel(const float* __restrict__ nf,
                      const float* __restrict__ ef,
                      const float* __restrict__ gf,
                      const int*   __restrict__ ei,
                      const int*   __restrict__ batch,
                      float*       __restrict__ out,
                      int E)
{
    extern __shared__ __align__(1024) char smem[];
    const uint32_t sbase = smem_u32(smem);
    const int tid  = threadIdx.x;
    const int wid  = tid >> 5;
    const int lane = tid & 31;
    const int e0   = blockIdx.x * TILE_E;

    int* s_src = (int*)(smem + SIDX);
    int* s_dst = s_src + TILE_E;
    int* s_g   = s_dst + TILE_E;
    {
        int e = e0 + tid;
        int s = 0, d = 0, g = 0;
        if (e < E) { s = ei[e]; d = ei[E + e]; g = batch[s]; }
        s_src[tid] = s; s_dst[tid] = d; s_g[tid] = g;
    }
    __syncthreads();

    const int wm = wid & 1;     // M group: rows wm*64
    const int wn = wid >> 1;    // N group: cols wn*64

    float acc[4][8][4];
    #pragma unroll
    for (int mt = 0; mt < 4; ++mt)
        #pragma unroll
        for (int nt = 0; nt < 8; ++nt)
            #pragma unroll
            for (int q = 0; q < 4; ++q)
                acc[mt][nt][q] = 0.0f;

    const int ecl = (e0 + tid < E) ? (e0 + tid) : 0;
    const int isrc = s_src[tid], idst = s_dst[tid], ig = s_g[tid];

    // ---- async producer: one K-chunk into stage st ----
    auto issue_chunk = [&](int c, int st) {
        const float* srcp;
        if (c < 4)       srcp = nf + (size_t)isrc * DN + c * KC;
        else if (c < 8)  srcp = nf + (size_t)idst * DN + (c - 4) * KC;
        else if (c < 10) srcp = ef + (size_t)ecl * DE + (c - 8) * KC;
        else             srcp = gf + (size_t)ig * DG + (c - 10) * KC;
        const uint32_t abase = sbase + st * STAGE_SZ;
        #pragma unroll
        for (int j = 0; j < 8; ++j)
            cp_async16(abase + SWZ128((uint32_t)(tid * 128 + j * 16)), srcp + j * 4);
        const uint32_t wbase = abase + 16384;
        const char* wsrc = (const char*)g_Wimg + (size_t)c * 16384 + tid * 128;
        #pragma unroll
        for (int j = 0; j < 8; ++j)
            cp_async16(wbase + tid * 128 + j * 16, wsrc + j * 16);
        asm volatile("cp.async.commit_group;" ::: "memory");
    };

    // prologue: fill stages 0..STAGES-2
    issue_chunk(0, 0);
    issue_chunk(1, 1);

    int st = 0;
    for (int c = 0; c < NCH; ++c) {
        // issue chunk c+2 into the stage freed at iteration c-1
        if (c + STAGES - 1 < NCH)
            issue_chunk(c + STAGES - 1, (st + STAGES - 1) % STAGES);

        // ensure chunk c has landed
        if (c + STAGES - 1 < NCH)      asm volatile("cp.async.wait_group 2;" ::: "memory");
        else if (c + STAGES - 2 < NCH) asm volatile("cp.async.wait_group 1;" ::: "memory");
        else                           asm volatile("cp.async.wait_group 0;" ::: "memory");
        __syncthreads();

        const uint32_t Abase = sbase + st * STAGE_SZ;
        const uint32_t Bbase = Abase + 16384;

        #pragma unroll
        for (int ks = 0; ks < 4; ++ks) {
            uint32_t af[4][4], bf[4][4];
            {
                const int rofs = ((lane >> 3) & 1) * 8 + (lane & 7);
                const int cofs = ks * 32 + ((lane >> 4) & 1) * 16;
                #pragma unroll
                for (int mt = 0; mt < 4; ++mt) {
                    const int row = wm * 64 + mt * 16 + rofs;
                    ldsm_x4(af[mt], Abase + SWZ128((uint32_t)(row * 128 + cofs)));
                }
            }
            {
                const int rofs = ((lane >> 4) & 1) * 8 + (lane & 7);
                const int cofs = ks * 32 + ((lane >> 3) & 1) * 16;
                #pragma unroll
                for (int nt = 0; nt < 4; ++nt) {
                    const int row = wn * 64 + nt * 16 + rofs;
                    ldsm_x4(bf[nt], Bbase + SWZ128((uint32_t)(row * 128 + cofs)));
                }
            }
            #pragma unroll
            for (int mt = 0; mt < 4; ++mt)
                #pragma unroll
                for (int nt = 0; nt < 4; ++nt) {
                    mma_tf32(acc[mt][2 * nt + 0], af[mt], bf[nt][0], bf[nt][1]);
                    mma_tf32(acc[mt][2 * nt + 1], af[mt], bf[nt][2], bf[nt][3]);
                }
        }
        __syncthreads();   // stage st free for reuse next iteration
        st = (st + 1) % STAGES;
    }

    // ---- epilogue: softplus + store ----
    #pragma unroll
    for (int mt = 0; mt < 4; ++mt) {
        const int r0 = e0 + wm * 64 + mt * 16 + (lane >> 2);
        const int r1 = r0 + 8;
        #pragma unroll
        for (int nt = 0; nt < 8; ++nt) {
            const int col = wn * 64 + nt * 8 + (lane & 3) * 2;
            if (r0 < E) {
                float2 o;
                o.x = softplus_shift(acc[mt][nt][0]);
                o.y = softplus_shift(acc[mt][nt][1]);
                *(float2*)(out + (size_t)r0 * H + col) = o;
            }
            if (r1 < E) {
                float2 o;
                o.x = softplus_shift(acc[mt][nt][2]);
                o.y = softplus_shift(acc[mt][nt][3]);
                *(float2*)(out + (size_t)r1 * H + col) = o;
            }
        }
    }
}

extern "C" void kernel_launch(void* const* d_in, const int* in_sizes, int n_in,
                              void* d_out, int out_size)
{
    const float* nf    = (const float*)d_in[0];
    const float* ef    = (const float*)d_in[1];
    const float* gf    = (const float*)d_in[2];
    const int*   ei    = (const int*)d_in[3];
    const int*   batch = (const int*)d_in[4];
    const float* W     = (const float*)d_in[5];
    float*       out   = (float*)d_out;

    const int E = in_sizes[1] / DE;   // edge_feats is [E, 64]

    static bool attr_set = false;
    if (!attr_set) {
        cudaFuncSetAttribute(edge_tf32_kernel,
                             cudaFuncAttributeMaxDynamicSharedMemorySize, SMEM_TOTAL);
        attr_set = true;
    }

    w_convert_kernel<<<(H * 384 + 255) / 256, 256>>>(W);
    const int grid = (E + TILE_E - 1) / TILE_E;
    edge_tf32_kernel<<<grid, THREADS, SMEM_TOTAL>>>(nf, ef, gf, ei, batch, out, E);
}

// round 7
// speedup vs baseline: 1.4599x; 1.4599x over previous
#include <cuda_runtime.h>
#include <cuda_fp16.h>
#include <cstdint>
#include <math.h>

// ============================================================================
// EdgeModel, persistent fp16 mma.sync kernel (baseline PTX; tcgen05 not
// available at the harness's compute_103 target):
//   out[e] = softplus( concat(nf[src], nf[dst], ef[e], gf[batch[src]]) @ W.T ) - log2
// fp16 single-pass (same 10-bit mantissa as tf32 -> same ~5e-4 rel err),
// fp32 accumulate. Persistent CTAs (1/SM): W (fp16, SW128-swizzled) resident
// in SMEM for the whole kernel; per 128-edge tile, A is gathered+converted in
// 6 K-slabs of 64 with LDG->reg prefetch overlapped against MMA compute.
// 256 threads = 8 warps, warp tile 32x64 over the 128x128 output tile.
// ============================================================================

#define DN 128
#define DE 64
#define DG 64
#define H  128
#define TILE_E 128
#define THREADS 256
#define NSLAB 6
#define LOG2F_CONST 0.6931471805599453f

#define SWZ128(off) ((off) ^ (((off) >> 3) & 0x70))

#define SLAB 16384                       // 128 rows x 64 f16 (128B rows)
#define OFF_A   (NSLAB * SLAB)           // 98304: 2 A slab buffers
#define OFF_IDX (OFF_A + 2 * SLAB)       // 131072
#define SMEM_TOTAL (OFF_IDX + 3 * TILE_E * 4)   // 132608

// W image: [6 slabs][128 n x 64 k] fp16, SW128-swizzled rows (128B)
__device__ uint16_t g_Wimg[NSLAB * 128 * 64];

__global__ void w_convert_kernel(const float* __restrict__ W) {
    int i = blockIdx.x * 256 + threadIdx.x;      // over 128*384
    if (i >= H * 384) return;
    int n = i / 384, k = i - n * 384;
    int c = k >> 6, kk = k & 63;
    __half h = __float2half_rn(W[i]);
    *(uint16_t*)((char*)g_Wimg + (size_t)c * SLAB + SWZ128((uint32_t)(n * 128 + kk * 2)))
        = __half_as_ushort(h);
}

__device__ __forceinline__ uint32_t smem_u32(const void* p) {
    uint32_t a;
    asm("{ .reg .u64 t; cvta.to.shared.u64 t, %1; cvt.u32.u64 %0, t; }" : "=r"(a) : "l"(p));
    return a;
}
__device__ __forceinline__ void ldsm_x4(uint32_t* r, uint32_t addr) {
    asm volatile("ldmatrix.sync.aligned.m8n8.x4.shared.b16 {%0,%1,%2,%3}, [%4];"
                 : "=r"(r[0]), "=r"(r[1]), "=r"(r[2]), "=r"(r[3]) : "r"(addr));
}
__device__ __forceinline__ void cp_async16(uint32_t dst, const void* src) {
    asm volatile("cp.async.cg.shared.global [%0], [%1], 16;" :: "r"(dst), "l"(src));
}
__device__ __forceinline__ void mma_f16(float* d, const uint32_t* a, uint32_t b0, uint32_t b1) {
    asm volatile(
        "mma.sync.aligned.m16n8k16.row.col.f32.f16.f16.f32 "
        "{%0,%1,%2,%3}, {%4,%5,%6,%7}, {%8,%9}, {%0,%1,%2,%3};"
        : "+f"(d[0]), "+f"(d[1]), "+f"(d[2]), "+f"(d[3])
        : "r"(a[0]), "r"(a[1]), "r"(a[2]), "r"(a[3]), "r"(b0), "r"(b1));
}
__device__ __forceinline__ float softplus_shift(float h) {
    return fmaxf(h, 0.0f) + __logf(1.0f + __expf(-fabsf(h))) - LOG2F_CONST;
}

__global__ __launch_bounds__(THREADS, 1)
void edge_f16_persistent(const float* __restrict__ nf,
                         const float* __restrict__ ef,
                         const float* __restrict__ gf,
                         const int*   __restrict__ ei,
                         const int*   __restrict__ batch,
                         float*       __restrict__ out,
                         int E, int ntiles)
{
    extern __shared__ __align__(1024) char smem[];
    const uint32_t sbase = smem_u32(smem);
    const int tid  = threadIdx.x;
    const int wid  = tid >> 5;
    const int lane = tid & 31;

    // ---- one-time: copy resident W (96KB, pre-swizzled fp16) ----
    {
        const char* wsrc = (const char*)g_Wimg;
        #pragma unroll
        for (int j = 0; j < 24; ++j)
            cp_async16(sbase + tid * 16 + j * 4096, wsrc + tid * 16 + j * 4096);
        asm volatile("cp.async.commit_group;" ::: "memory");
        asm volatile("cp.async.wait_group 0;" ::: "memory");
    }
    __syncthreads();

    int* s_src = (int*)(smem + OFF_IDX);
    int* s_dst = s_src + TILE_E;
    int* s_g   = s_dst + TILE_E;

    const int wm = wid & 3;        // M group: rows wm*32
    const int wn = wid >> 2;       // N group: cols wn*64
    const int r  = tid >> 1;       // A-gather row (0..127)
    const int q  = tid & 1;        // A-gather half (32 floats)

    for (int tile = blockIdx.x; tile < ntiles; tile += gridDim.x) {
        const int e0 = tile * TILE_E;

        // ---- indices ----
        if (tid < TILE_E) {
            int e = e0 + tid;
            int s = 0, d = 0, g = 0;
            if (e < E) { s = ei[e]; d = ei[E + e]; g = batch[s]; }
            s_src[tid] = s; s_dst[tid] = d; s_g[tid] = g;
        }
        __syncthreads();

        const int isrc = s_src[r], idst = s_dst[r], ig = s_g[r];
        const int ecl  = (e0 + r < E) ? (e0 + r) : 0;

        // per-slab source base (64 floats per row)
        const float* slabp[NSLAB];
        slabp[0] = nf + (size_t)isrc * DN;
        slabp[1] = nf + (size_t)isrc * DN + 64;
        slabp[2] = nf + (size_t)idst * DN;
        slabp[3] = nf + (size_t)idst * DN + 64;
        slabp[4] = ef + (size_t)ecl * DE;
        slabp[5] = gf + (size_t)ig * DG;

        float4 v[8];
        // preload + convert slab 0 into A buffer 0
        {
            const float4* p = (const float4*)slabp[0];
            #pragma unroll
            for (int j = 0; j < 8; ++j) v[j] = p[q * 8 + j];
            char* ab = smem + OFF_A;                      // buffer 0
            #pragma unroll
            for (int j = 0; j < 8; ++j) {
                __half2 h01 = __floats2half2_rn(v[j].x, v[j].y);
                __half2 h23 = __floats2half2_rn(v[j].z, v[j].w);
                uint2 pk; pk.x = *(uint32_t*)&h01; pk.y = *(uint32_t*)&h23;
                *(uint2*)(ab + SWZ128((uint32_t)(r * 128 + q * 64 + j * 8))) = pk;
            }
        }
        __syncthreads();

        float acc[2][8][4];
        #pragma unroll
        for (int mt = 0; mt < 2; ++mt)
            #pragma unroll
            for (int nt = 0; nt < 8; ++nt)
                #pragma unroll
                for (int z = 0; z < 4; ++z) acc[mt][nt][z] = 0.0f;

        #pragma unroll
        for (int c = 0; c < NSLAB; ++c) {
            // issue next slab's global loads early (latency hides under MMA)
            if (c + 1 < NSLAB) {
                const float4* p = (const float4*)slabp[c + 1];
                #pragma unroll
                for (int j = 0; j < 8; ++j) v[j] = p[q * 8 + j];
            }

            // ---- compute slab c: W slab c (resident), A buffer c&1 ----
            const uint32_t Abase = sbase + OFF_A + (c & 1) * SLAB;
            const uint32_t Bbase = sbase + c * SLAB;
            #pragma unroll
            for (int ks = 0; ks < 4; ++ks) {
                uint32_t af[2][4], bf[4][4];
                {
                    const int rofs = lane & 15;
                    const int cofs = ks * 32 + ((lane >> 4) & 1) * 16;
                    #pragma unroll
                    for (int mt = 0; mt < 2; ++mt) {
                        const int row = wm * 32 + mt * 16 + rofs;
                        ldsm_x4(af[mt], Abase + SWZ128((uint32_t)(row * 128 + cofs)));
                    }
                }
                {
                    const int rofs = (lane & 7) + ((lane >> 4) & 1) * 8;
                    const int cofs = ks * 32 + ((lane >> 3) & 1) * 16;
                    #pragma unroll
                    for (int nt = 0; nt < 4; ++nt) {
                        const int row = wn * 64 + nt * 16 + rofs;
                        ldsm_x4(bf[nt], Bbase + SWZ128((uint32_t)(row * 128 + cofs)));
                    }
                }
                #pragma unroll
                for (int mt = 0; mt < 2; ++mt)
                    #pragma unroll
                    for (int nt = 0; nt < 4; ++nt) {
                        mma_f16(acc[mt][2 * nt + 0], af[mt], bf[nt][0], bf[nt][1]);
                        mma_f16(acc[mt][2 * nt + 1], af[mt], bf[nt][2], bf[nt][3]);
                    }
            }

            // convert + store next slab, then barrier
            if (c + 1 < NSLAB) {
                char* ab = smem + OFF_A + ((c + 1) & 1) * SLAB;
                #pragma unroll
                for (int j = 0; j < 8; ++j) {
                    __half2 h01 = __floats2half2_rn(v[j].x, v[j].y);
                    __half2 h23 = __floats2half2_rn(v[j].z, v[j].w);
                    uint2 pk; pk.x = *(uint32_t*)&h01; pk.y = *(uint32_t*)&h23;
                    *(uint2*)(ab + SWZ128((uint32_t)(r * 128 + q * 64 + j * 8))) = pk;
                }
            }
            __syncthreads();
        }

        // ---- epilogue: softplus + store (fire-and-forget STG) ----
        #pragma unroll
        for (int mt = 0; mt < 2; ++mt) {
            const int r0 = e0 + wm * 32 + mt * 16 + (lane >> 2);
            const int r1 = r0 + 8;
            #pragma unroll
            for (int nt = 0; nt < 8; ++nt) {
                const int col = wn * 64 + nt * 8 + (lane & 3) * 2;
                if (r0 < E) {
                    float2 o;
                    o.x = softplus_shift(acc[mt][nt][0]);
                    o.y = softplus_shift(acc[mt][nt][1]);
                    *(float2*)(out + (size_t)r0 * H + col) = o;
                }
                if (r1 < E) {
                    float2 o;
                    o.x = softplus_shift(acc[mt][nt][2]);
                    o.y = softplus_shift(acc[mt][nt][3]);
                    *(float2*)(out + (size_t)r1 * H + col) = o;
                }
            }
        }
        __syncthreads();   // protect idx/A buffers before next tile overwrites
    }
}

extern "C" void kernel_launch(void* const* d_in, const int* in_sizes, int n_in,
                              void* d_out, int out_size)
{
    const float* nf    = (const float*)d_in[0];
    const float* ef    = (const float*)d_in[1];
    const float* gf    = (const float*)d_in[2];
    const int*   ei    = (const int*)d_in[3];
    const int*   batch = (const int*)d_in[4];
    const float* W     = (const float*)d_in[5];
    float*       out   = (float*)d_out;

    const int E = in_sizes[1] / DE;              // edge_feats is [E, 64]
    const int ntiles = (E + TILE_E - 1) / TILE_E;

    static int sms = 0;
    if (sms == 0) {
        cudaDeviceGetAttribute(&sms, cudaDevAttrMultiProcessorCount, 0);
        if (sms <= 0) sms = 148;
        cudaFuncSetAttribute(edge_f16_persistent,
                             cudaFuncAttributeMaxDynamicSharedMemorySize, SMEM_TOTAL);
    }

    w_convert_kernel<<<(H * 384 + 255) / 256, 256>>>(W);
    edge_f16_persistent<<<sms, THREADS, SMEM_TOTAL>>>(nf, ef, gf, ei, batch, out, E, ntiles);
}

// round 8
// speedup vs baseline: 1.7442x; 1.1947x over previous
#include <cuda_runtime.h>
#include <cuda_fp16.h>
#include <cstdint>
#include <math.h>

// ============================================================================
// EdgeModel, persistent warp-specialized fp16 mma.sync kernel (baseline PTX):
//   out[e] = softplus( concat(nf[src], nf[dst], ef[e], gf[batch[src]]) @ W.T ) - log2
// 8 warps: 4 producers (gather fp32 -> fp16 -> SMEM slabs, mbarrier-signaled),
//          4 consumers (ldmatrix + mma.m16n8k16.f16, warp tile 64x64, softplus).
// W fp16 SW128-swizzled resident in SMEM (96KB); 6 slab ring (96KB) = 1 tile
// of producer look-ahead. No __syncthreads in the steady-state loop.
// ============================================================================

#define DN 128
#define DE 64
#define DG 64
#define H  128
#define TILE_E 128
#define THREADS 256
#define NSLAB 6
#define SLAB 16384                       // 128 rows x 64 f16 (128B rows)
#define OFF_RING (NSLAB * SLAB)          // 98304
#define OFF_MBAR (OFF_RING + NSLAB * SLAB)   // 196608
#define SMEM_TOTAL (OFF_MBAR + 128)
#define LOG2F_CONST 0.6931471805599453f

#define SWZ128(off) ((off) ^ (((off) >> 3) & 0x70))

// W image: [6 slabs][128 n x 64 k] fp16, SW128-swizzled rows (128B)
__device__ uint16_t g_Wimg[NSLAB * 128 * 64];

__global__ void w_convert_kernel(const float* __restrict__ W) {
    int i = blockIdx.x * 256 + threadIdx.x;      // over 128*384
    if (i >= H * 384) return;
    int n = i / 384, k = i - n * 384;
    int c = k >> 6, kk = k & 63;
    __half h = __float2half_rn(W[i]);
    *(uint16_t*)((char*)g_Wimg + (size_t)c * SLAB + SWZ128((uint32_t)(n * 128 + kk * 2)))
        = __half_as_ushort(h);
}

__device__ __forceinline__ uint32_t smem_u32(const void* p) {
    uint32_t a;
    asm("{ .reg .u64 t; cvta.to.shared.u64 t, %1; cvt.u32.u64 %0, t; }" : "=r"(a) : "l"(p));
    return a;
}
__device__ __forceinline__ void ldsm_x4(uint32_t* r, uint32_t addr) {
    asm volatile("ldmatrix.sync.aligned.m8n8.x4.shared.b16 {%0,%1,%2,%3}, [%4];"
                 : "=r"(r[0]), "=r"(r[1]), "=r"(r[2]), "=r"(r[3]) : "r"(addr));
}
__device__ __forceinline__ void cp_async16(uint32_t dst, const void* src) {
    asm volatile("cp.async.cg.shared.global [%0], [%1], 16;" :: "r"(dst), "l"(src));
}
__device__ __forceinline__ void mma_f16(float* d, const uint32_t* a, uint32_t b0, uint32_t b1) {
    asm volatile(
        "mma.sync.aligned.m16n8k16.row.col.f32.f16.f16.f32 "
        "{%0,%1,%2,%3}, {%4,%5,%6,%7}, {%8,%9}, {%0,%1,%2,%3};"
        : "+f"(d[0]), "+f"(d[1]), "+f"(d[2]), "+f"(d[3])
        : "r"(a[0]), "r"(a[1]), "r"(a[2]), "r"(a[3]), "r"(b0), "r"(b1));
}
__device__ __forceinline__ float softplus_shift(float h) {
    return fmaxf(h, 0.0f) + __logf(1.0f + __expf(-fabsf(h))) - LOG2F_CONST;
}

#define MBAR_INIT(mbar, cnt) \
    asm volatile("mbarrier.init.shared.b64 [%0], %1;" \
        :: "r"((uint32_t)(mbar)), "r"((uint32_t)(cnt)) : "memory")
#define MBAR_ARRIVE(mbar) \
    asm volatile("mbarrier.arrive.shared.b64 _, [%0];" :: "r"((uint32_t)(mbar)) : "memory")
#define MBAR_WAIT(mbar, parity) do { \
    uint32_t _m = (uint32_t)(mbar); uint32_t _p = (uint32_t)(parity); uint32_t _d; \
    asm volatile("{\n\t.reg .pred p;\n\t" \
        "mbarrier.try_wait.parity.acquire.cta.shared::cta.b64 p, [%1], %2;\n\t" \
        "selp.b32 %0, 1, 0, p;\n\t}" : "=r"(_d) : "r"(_m), "r"(_p) : "memory"); \
    if (!_d) { \
        asm volatile("{\n\t.reg .pred P1;\n\tWL_%=:\n\t" \
            "mbarrier.try_wait.parity.acquire.cta.shared::cta.b64 P1, [%0], %1, 0x989680;\n\t" \
            "@P1 bra.uni WD_%=;\n\tbra.uni WL_%=;\n\tWD_%=:\n\t}" \
            :: "r"(_m), "r"(_p) : "memory"); \
    } } while (0)

__global__ __launch_bounds__(THREADS, 1)
void edge_ws_kernel(const float* __restrict__ nf,
                    const float* __restrict__ ef,
                    const float* __restrict__ gf,
                    const int*   __restrict__ ei,
                    const int*   __restrict__ batch,
                    float*       __restrict__ out,
                    int E, int ntiles)
{
    extern __shared__ __align__(1024) char smem[];
    const uint32_t sbase = smem_u32(smem);
    const int tid  = threadIdx.x;
    const int wid  = tid >> 5;
    const int lane = tid & 31;

    // ---- one-time: resident W copy (96KB) + mbarrier init ----
    {
        const char* wsrc = (const char*)g_Wimg;
        #pragma unroll
        for (int j = 0; j < 24; ++j)
            cp_async16(sbase + tid * 16 + j * 4096, wsrc + tid * 16 + j * 4096);
        asm volatile("cp.async.commit_group;" ::: "memory");
        asm volatile("cp.async.wait_group 0;" ::: "memory");
    }
    if (tid == 0) {
        #pragma unroll
        for (int s = 0; s < NSLAB; ++s) {
            MBAR_INIT(sbase + OFF_MBAR + s * 8, 128);        // full[s]
            MBAR_INIT(sbase + OFF_MBAR + 48 + s * 8, 128);   // empty[s]
        }
    }
    __syncthreads();   // last block-wide barrier

    if (wid >= 4) {
        // ======================= PRODUCER (warps 4-7) =======================
        const int pr = (wid - 4) * 32 + lane;     // row 0..127 of the tile
        char* ring = smem + OFF_RING;
        int tcnt = 0;
        for (int tile = blockIdx.x; tile < ntiles; tile += gridDim.x, ++tcnt) {
            const int e  = tile * TILE_E + pr;
            const int ee = (e < E) ? e : 0;
            const int isrc = ei[ee];
            const int idst = ei[E + ee];
            const int ig   = batch[isrc];
            const float* base[NSLAB];
            base[0] = nf + (size_t)isrc * DN;
            base[1] = nf + (size_t)isrc * DN + 64;
            base[2] = nf + (size_t)idst * DN;
            base[3] = nf + (size_t)idst * DN + 64;
            base[4] = ef + (size_t)ee * DE;
            base[5] = gf + (size_t)ig * DG;

            float4 v[2][16];
            #pragma unroll
            for (int j = 0; j < 16; ++j) v[0][j] = ((const float4*)base[0])[j];

            const uint32_t ew_par = (tcnt & 1) ^ 1;   // parity for empty waits
            #pragma unroll
            for (int sl = 0; sl < NSLAB; ++sl) {
                // issue next slab's loads before touching this one
                if (sl + 1 < NSLAB) {
                    #pragma unroll
                    for (int j = 0; j < 16; ++j)
                        v[(sl + 1) & 1][j] = ((const float4*)base[sl + 1])[j];
                }
                if (tcnt > 0) MBAR_WAIT(sbase + OFF_MBAR + 48 + sl * 8, ew_par);
                char* dst = ring + sl * SLAB;
                #pragma unroll
                for (int j = 0; j < 16; ++j) {
                    float4 w = v[sl & 1][j];
                    __half2 h01 = __floats2half2_rn(w.x, w.y);
                    __half2 h23 = __floats2half2_rn(w.z, w.w);
                    uint2 pk; pk.x = *(uint32_t*)&h01; pk.y = *(uint32_t*)&h23;
                    *(uint2*)(dst + SWZ128((uint32_t)(pr * 128 + j * 8))) = pk;
                }
                MBAR_ARRIVE(sbase + OFF_MBAR + sl * 8);
            }
        }
    } else {
        // ======================= CONSUMER (warps 0-3) =======================
        const int wm = wid & 1;       // rows wm*64
        const int wn = wid >> 1;      // cols wn*64
        int tcnt = 0;
        for (int tile = blockIdx.x; tile < ntiles; tile += gridDim.x, ++tcnt) {
            const int e0 = tile * TILE_E;
            float acc[4][8][4];
            #pragma unroll
            for (int mt = 0; mt < 4; ++mt)
                #pragma unroll
                for (int nt = 0; nt < 8; ++nt)
                    #pragma unroll
                    for (int z = 0; z < 4; ++z) acc[mt][nt][z] = 0.0f;

            const uint32_t fw_par = tcnt & 1;
            #pragma unroll 1
            for (int sl = 0; sl < NSLAB; ++sl) {
                MBAR_WAIT(sbase + OFF_MBAR + sl * 8, fw_par);
                const uint32_t Abase = sbase + OFF_RING + sl * SLAB;
                const uint32_t Bbase = sbase + sl * SLAB;
                #pragma unroll
                for (int ks = 0; ks < 4; ++ks) {
                    uint32_t af[4][4], bf[4][4];
                    {
                        const int rofs = lane & 15;
                        const int cofs = ks * 32 + ((lane >> 4) & 1) * 16;
                        #pragma unroll
                        for (int mt = 0; mt < 4; ++mt) {
                            const int row = wm * 64 + mt * 16 + rofs;
                            ldsm_x4(af[mt], Abase + SWZ128((uint32_t)(row * 128 + cofs)));
                        }
                    }
                    {
                        const int rofs = (lane & 7) + ((lane >> 4) & 1) * 8;
                        const int cofs = ks * 32 + ((lane >> 3) & 1) * 16;
                        #pragma unroll
                        for (int nt = 0; nt < 4; ++nt) {
                            const int row = wn * 64 + nt * 16 + rofs;
                            ldsm_x4(bf[nt], Bbase + SWZ128((uint32_t)(row * 128 + cofs)));
                        }
                    }
                    #pragma unroll
                    for (int mt = 0; mt < 4; ++mt)
                        #pragma unroll
                        for (int nt = 0; nt < 4; ++nt) {
                            mma_f16(acc[mt][2 * nt + 0], af[mt], bf[nt][0], bf[nt][1]);
                            mma_f16(acc[mt][2 * nt + 1], af[mt], bf[nt][2], bf[nt][3]);
                        }
                }
                MBAR_ARRIVE(sbase + OFF_MBAR + 48 + sl * 8);
            }

            // ---- epilogue: softplus + store (overlaps next tile's gather) ----
            #pragma unroll
            for (int mt = 0; mt < 4; ++mt) {
                const int r0 = e0 + wm * 64 + mt * 16 + (lane >> 2);
                const int r1 = r0 + 8;
                #pragma unroll
                for (int nt = 0; nt < 8; ++nt) {
                    const int col = wn * 64 + nt * 8 + (lane & 3) * 2;
                    if (r0 < E) {
                        float2 o;
                        o.x = softplus_shift(acc[mt][nt][0]);
                        o.y = softplus_shift(acc[mt][nt][1]);
                        *(float2*)(out + (size_t)r0 * H + col) = o;
                    }
                    if (r1 < E) {
                        float2 o;
                        o.x = softplus_shift(acc[mt][nt][2]);
                        o.y = softplus_shift(acc[mt][nt][3]);
                        *(float2*)(out + (size_t)r1 * H + col) = o;
                    }
                }
            }
        }
    }
}

extern "C" void kernel_launch(void* const* d_in, const int* in_sizes, int n_in,
                              void* d_out, int out_size)
{
    const float* nf    = (const float*)d_in[0];
    const float* ef    = (const float*)d_in[1];
    const float* gf    = (const float*)d_in[2];
    const int*   ei    = (const int*)d_in[3];
    const int*   batch = (const int*)d_in[4];
    const float* W     = (const float*)d_in[5];
    float*       out   = (float*)d_out;

    const int E = in_sizes[1] / DE;              // edge_feats is [E, 64]
    const int ntiles = (E + TILE_E - 1) / TILE_E;

    static int sms = 0;
    if (sms == 0) {
        cudaDeviceGetAttribute(&sms, cudaDevAttrMultiProcessorCount, 0);
        if (sms <= 0) sms = 148;
        cudaFuncSetAttribute(edge_ws_kernel,
                             cudaFuncAttributeMaxDynamicSharedMemorySize, SMEM_TOTAL);
    }

    w_convert_kernel<<<(H * 384 + 255) / 256, 256>>>(W);
    edge_ws_kernel<<<sms, THREADS, SMEM_TOTAL>>>(nf, ef, gf, ei, batch, out, E, ntiles);
}

// round 9
// speedup vs baseline: 2.2759x; 1.3049x over previous
#include <cuda_runtime.h>
#include <cuda_fp16.h>
#include <cstdint>
#include <math.h>

// ============================================================================
// EdgeModel, persistent warp-specialized fp16 mma.sync kernel (baseline PTX):
//   out[e] = softplus( concat(nf[src], nf[dst], ef[e], gf[batch[src]]) @ W.T ) - log2
// R9: coalesced gather. nf/gf pre-converted to fp16 row images (nf row = 128B
// = 1 line, L2-resident); producers issue cp.async with 8 lanes/row (4 lines
// per LDG instr vs 32 before). ef slab stays fp32 LDG+cvt+STS (contiguous).
// 4 producer + 4 consumer warps, mbarrier slab ring, W fp16 resident in SMEM.
// ============================================================================

#define DN 128
#define DE 64
#define DG 64
#define H  128
#define TILE_E 128
#define THREADS 256
#define NSLAB 6
#define SLAB 16384                       // 128 rows x 64 f16 (128B rows)
#define OFF_RING (NSLAB * SLAB)          // 98304
#define OFF_IDX  (OFF_RING + NSLAB * SLAB)   // 196608
#define OFF_MBAR (OFF_IDX + 3 * TILE_E * 4)
#define SMEM_TOTAL (OFF_MBAR + 128)
#define LOG2F_CONST 0.6931471805599453f

#define SWZ128(off) ((off) ^ (((off) >> 3) & 0x70))

#define N_CAP 50000
#define G_CAP 256

// W image: [6 slabs][128 n x 64 k] fp16, SW128-swizzled rows (128B)
__device__ uint16_t g_Wimg[NSLAB * 128 * 64];
// fp16 row images (plain row-major): nf [N][128], gf [G][64]
__device__ uint16_t g_nfh[N_CAP * DN];
__device__ uint16_t g_gfh[G_CAP * DG];

__global__ void w_convert_kernel(const float* __restrict__ W) {
    int i = blockIdx.x * 256 + threadIdx.x;      // over 128*384
    if (i >= H * 384) return;
    int n = i / 384, k = i - n * 384;
    int c = k >> 6, kk = k & 63;
    __half h = __float2half_rn(W[i]);
    *(uint16_t*)((char*)g_Wimg + (size_t)c * SLAB + SWZ128((uint32_t)(n * 128 + kk * 2)))
        = __half_as_ushort(h);
}

__global__ void nf_convert_kernel(const float* __restrict__ nf, int total4) {
    int i = blockIdx.x * 256 + threadIdx.x;      // over N*128/4
    if (i >= total4) return;
    float4 v = ((const float4*)nf)[i];
    __half2 a = __floats2half2_rn(v.x, v.y);
    __half2 b = __floats2half2_rn(v.z, v.w);
    uint2 pk; pk.x = *(uint32_t*)&a; pk.y = *(uint32_t*)&b;
    ((uint2*)g_nfh)[i] = pk;
}

__global__ void gf_convert_kernel(const float* __restrict__ gf, int total4) {
    int i = blockIdx.x * 256 + threadIdx.x;      // over G*64/4
    if (i >= total4) return;
    float4 v = ((const float4*)gf)[i];
    __half2 a = __floats2half2_rn(v.x, v.y);
    __half2 b = __floats2half2_rn(v.z, v.w);
    uint2 pk; pk.x = *(uint32_t*)&a; pk.y = *(uint32_t*)&b;
    ((uint2*)g_gfh)[i] = pk;
}

__device__ __forceinline__ uint32_t smem_u32(const void* p) {
    uint32_t a;
    asm("{ .reg .u64 t; cvta.to.shared.u64 t, %1; cvt.u32.u64 %0, t; }" : "=r"(a) : "l"(p));
    return a;
}
__device__ __forceinline__ void ldsm_x4(uint32_t* r, uint32_t addr) {
    asm volatile("ldmatrix.sync.aligned.m8n8.x4.shared.b16 {%0,%1,%2,%3}, [%4];"
                 : "=r"(r[0]), "=r"(r[1]), "=r"(r[2]), "=r"(r[3]) : "r"(addr));
}
__device__ __forceinline__ void cp_async16(uint32_t dst, const void* src) {
    asm volatile("cp.async.cg.shared.global [%0], [%1], 16;" :: "r"(dst), "l"(src));
}
__device__ __forceinline__ void mma_f16(float* d, const uint32_t* a, uint32_t b0, uint32_t b1) {
    asm volatile(
        "mma.sync.aligned.m16n8k16.row.col.f32.f16.f16.f32 "
        "{%0,%1,%2,%3}, {%4,%5,%6,%7}, {%8,%9}, {%0,%1,%2,%3};"
        : "+f"(d[0]), "+f"(d[1]), "+f"(d[2]), "+f"(d[3])
        : "r"(a[0]), "r"(a[1]), "r"(a[2]), "r"(a[3]), "r"(b0), "r"(b1));
}
__device__ __forceinline__ float softplus_shift(float h) {
    return fmaxf(h, 0.0f) + __logf(1.0f + __expf(-fabsf(h))) - LOG2F_CONST;
}

#define MBAR_INIT(mbar, cnt) \
    asm volatile("mbarrier.init.shared.b64 [%0], %1;" \
        :: "r"((uint32_t)(mbar)), "r"((uint32_t)(cnt)) : "memory")
#define MBAR_ARRIVE(mbar) \
    asm volatile("mbarrier.arrive.shared.b64 _, [%0];" :: "r"((uint32_t)(mbar)) : "memory")
#define MBAR_WAIT(mbar, parity) do { \
    uint32_t _m = (uint32_t)(mbar); uint32_t _p = (uint32_t)(parity); uint32_t _d; \
    asm volatile("{\n\t.reg .pred p;\n\t" \
        "mbarrier.try_wait.parity.acquire.cta.shared::cta.b64 p, [%1], %2;\n\t" \
        "selp.b32 %0, 1, 0, p;\n\t}" : "=r"(_d) : "r"(_m), "r"(_p) : "memory"); \
    if (!_d) { \
        asm volatile("{\n\t.reg .pred P1;\n\tWL_%=:\n\t" \
            "mbarrier.try_wait.parity.acquire.cta.shared::cta.b64 P1, [%0], %1, 0x989680;\n\t" \
            "@P1 bra.uni WD_%=;\n\tbra.uni WL_%=;\n\tWD_%=:\n\t}" \
            :: "r"(_m), "r"(_p) : "memory"); \
    } } while (0)

__global__ __launch_bounds__(THREADS, 1)
void edge_ws_kernel(const float* __restrict__ ef,
                    const int*   __restrict__ ei,
                    const int*   __restrict__ batch,
                    float*       __restrict__ out,
                    int E, int ntiles)
{
    extern __shared__ __align__(1024) char smem[];
    const uint32_t sbase = smem_u32(smem);
    const int tid  = threadIdx.x;
    const int wid  = tid >> 5;
    const int lane = tid & 31;

    // ---- one-time: resident W copy (96KB) + mbarrier init ----
    {
        const char* wsrc = (const char*)g_Wimg;
        #pragma unroll
        for (int j = 0; j < 24; ++j)
            cp_async16(sbase + tid * 16 + j * 4096, wsrc + tid * 16 + j * 4096);
        asm volatile("cp.async.commit_group;" ::: "memory");
        asm volatile("cp.async.wait_group 0;" ::: "memory");
    }
    if (tid == 0) {
        #pragma unroll
        for (int s = 0; s < NSLAB; ++s) {
            MBAR_INIT(sbase + OFF_MBAR + s * 8, 128);        // full[s]
            MBAR_INIT(sbase + OFF_MBAR + 48 + s * 8, 128);   // empty[s]
        }
    }
    __syncthreads();   // last block-wide barrier

    if (wid >= 4) {
        // ======================= PRODUCER (warps 4-7) =======================
        const int pw    = wid - 4;
        const int wrow0 = pw * 32;
        int* s_src = (int*)(smem + OFF_IDX);
        int* s_dst = s_src + TILE_E;
        int* s_g   = s_dst + TILE_E;
        const int l8 = lane & 7;       // 16B chunk within row
        const int r4 = lane >> 3;      // row within 4-row group
        int tcnt = 0;
        for (int tile = blockIdx.x; tile < ntiles; tile += gridDim.x, ++tcnt) {
            // stage indices (warp-local rows wrow0..wrow0+31)
            {
                const int e  = tile * TILE_E + wrow0 + lane;
                const int ee = (e < E) ? e : 0;
                const int is = ei[ee];
                s_src[wrow0 + lane] = is;
                s_dst[wrow0 + lane] = ei[E + ee];
                s_g[wrow0 + lane]   = batch[is];
            }
            __syncwarp();

            const uint32_t ew_par = (tcnt & 1) ^ 1;
            const uint32_t ring   = sbase + OFF_RING;

            #pragma unroll
            for (int sl = 0; sl < NSLAB; ++sl) {
                if (tcnt > 0) MBAR_WAIT(sbase + OFF_MBAR + 48 + sl * 8, ew_par);
                if (sl != 4) {
                    #pragma unroll
                    for (int g = 0; g < 8; ++g) {
                        const int r = wrow0 + g * 4 + r4;
                        int idx;
                        if (sl < 2)      idx = s_src[r];
                        else if (sl < 4) idx = s_dst[r];
                        else             idx = s_g[r];
                        const char* src = (sl < 4)
                            ? (const char*)g_nfh + (size_t)idx * 256 + (sl & 1) * 128 + l8 * 16
                            : (const char*)g_gfh + (size_t)idx * 128 + l8 * 16;
                        cp_async16(ring + sl * SLAB + SWZ128((uint32_t)(r * 128 + l8 * 16)), src);
                    }
                } else {
                    // ef slab: contiguous fp32 rows, convert in-flight
                    #pragma unroll
                    for (int g = 0; g < 8; ++g) {
                        const int r  = wrow0 + g * 4 + r4;
                        const int e  = tile * TILE_E + r;
                        const int ee = (e < E) ? e : 0;
                        const float* rp = ef + (size_t)ee * DE;
                        float4 v0 = *(const float4*)(rp + l8 * 4);
                        float4 v1 = *(const float4*)(rp + 32 + l8 * 4);
                        __half2 a0 = __floats2half2_rn(v0.x, v0.y);
                        __half2 b0 = __floats2half2_rn(v0.z, v0.w);
                        __half2 a1 = __floats2half2_rn(v1.x, v1.y);
                        __half2 b1 = __floats2half2_rn(v1.z, v1.w);
                        uint2 p0; p0.x = *(uint32_t*)&a0; p0.y = *(uint32_t*)&b0;
                        uint2 p1; p1.x = *(uint32_t*)&a1; p1.y = *(uint32_t*)&b1;
                        char* dst = smem + OFF_RING + sl * SLAB;
                        *(uint2*)(dst + SWZ128((uint32_t)(r * 128 + l8 * 8)))      = p0;
                        *(uint2*)(dst + SWZ128((uint32_t)(r * 128 + 64 + l8 * 8))) = p1;
                    }
                }
                asm volatile("cp.async.commit_group;" ::: "memory");
            }
            // drain groups oldest-first, signal full
            asm volatile("cp.async.wait_group 5;" ::: "memory");
            MBAR_ARRIVE(sbase + OFF_MBAR + 0 * 8);
            asm volatile("cp.async.wait_group 4;" ::: "memory");
            MBAR_ARRIVE(sbase + OFF_MBAR + 1 * 8);
            asm volatile("cp.async.wait_group 3;" ::: "memory");
            MBAR_ARRIVE(sbase + OFF_MBAR + 2 * 8);
            asm volatile("cp.async.wait_group 2;" ::: "memory");
            MBAR_ARRIVE(sbase + OFF_MBAR + 3 * 8);
            asm volatile("cp.async.wait_group 1;" ::: "memory");
            MBAR_ARRIVE(sbase + OFF_MBAR + 4 * 8);
            asm volatile("cp.async.wait_group 0;" ::: "memory");
            MBAR_ARRIVE(sbase + OFF_MBAR + 5 * 8);
        }
    } else {
        // ======================= CONSUMER (warps 0-3) =======================
        const int wm = wid & 1;       // rows wm*64
        const int wn = wid >> 1;      // cols wn*64
        int tcnt = 0;
        for (int tile = blockIdx.x; tile < ntiles; tile += gridDim.x, ++tcnt) {
            const int e0 = tile * TILE_E;
            float acc[4][8][4];
            #pragma unroll
            for (int mt = 0; mt < 4; ++mt)
                #pragma unroll
                for (int nt = 0; nt < 8; ++nt)
                    #pragma unroll
                    for (int z = 0; z < 4; ++z) acc[mt][nt][z] = 0.0f;

            const uint32_t fw_par = tcnt & 1;
            #pragma unroll 1
            for (int sl = 0; sl < NSLAB; ++sl) {
                MBAR_WAIT(sbase + OFF_MBAR + sl * 8, fw_par);
                const uint32_t Abase = sbase + OFF_RING + sl * SLAB;
                const uint32_t Bbase = sbase + sl * SLAB;
                #pragma unroll
                for (int ks = 0; ks < 4; ++ks) {
                    uint32_t af[4][4], bf[4][4];
                    {
                        const int rofs = lane & 15;
                        const int cofs = ks * 32 + ((lane >> 4) & 1) * 16;
                        #pragma unroll
                        for (int mt = 0; mt < 4; ++mt) {
                            const int row = wm * 64 + mt * 16 + rofs;
                            ldsm_x4(af[mt], Abase + SWZ128((uint32_t)(row * 128 + cofs)));
                        }
                    }
                    {
                        const int rofs = (lane & 7) + ((lane >> 4) & 1) * 8;
                        const int cofs = ks * 32 + ((lane >> 3) & 1) * 16;
                        #pragma unroll
                        for (int nt = 0; nt < 4; ++nt) {
                            const int row = wn * 64 + nt * 16 + rofs;
                            ldsm_x4(bf[nt], Bbase + SWZ128((uint32_t)(row * 128 + cofs)));
                        }
                    }
                    #pragma unroll
                    for (int mt = 0; mt < 4; ++mt)
                        #pragma unroll
                        for (int nt = 0; nt < 4; ++nt) {
                            mma_f16(acc[mt][2 * nt + 0], af[mt], bf[nt][0], bf[nt][1]);
                            mma_f16(acc[mt][2 * nt + 1], af[mt], bf[nt][2], bf[nt][3]);
                        }
                }
                MBAR_ARRIVE(sbase + OFF_MBAR + 48 + sl * 8);
            }

            // ---- epilogue: softplus + store (overlaps next tile's gather) ----
            #pragma unroll
            for (int mt = 0; mt < 4; ++mt) {
                const int r0 = e0 + wm * 64 + mt * 16 + (lane >> 2);
                const int r1 = r0 + 8;
                #pragma unroll
                for (int nt = 0; nt < 8; ++nt) {
                    const int col = wn * 64 + nt * 8 + (lane & 3) * 2;
                    if (r0 < E) {
                        float2 o;
                        o.x = softplus_shift(acc[mt][nt][0]);
                        o.y = softplus_shift(acc[mt][nt][1]);
                        *(float2*)(out + (size_t)r0 * H + col) = o;
                    }
                    if (r1 < E) {
                        float2 o;
                        o.x = softplus_shift(acc[mt][nt][2]);
                        o.y = softplus_shift(acc[mt][nt][3]);
                        *(float2*)(out + (size_t)r1 * H + col) = o;
                    }
                }
            }
        }
    }
}

extern "C" void kernel_launch(void* const* d_in, const int* in_sizes, int n_in,
                              void* d_out, int out_size)
{
    const float* nf    = (const float*)d_in[0];
    const float* ef    = (const float*)d_in[1];
    const float* gf    = (const float*)d_in[2];
    const int*   ei    = (const int*)d_in[3];
    const int*   batch = (const int*)d_in[4];
    const float* W     = (const float*)d_in[5];
    float*       out   = (float*)d_out;

    const int E = in_sizes[1] / DE;              // edge_feats is [E, 64]
    const int N = in_sizes[0] / DN;
    const int G = in_sizes[2] / DG;
    const int ntiles = (E + TILE_E - 1) / TILE_E;

    static int sms = 0;
    if (sms == 0) {
        cudaDeviceGetAttribute(&sms, cudaDevAttrMultiProcessorCount, 0);
        if (sms <= 0) sms = 148;
        cudaFuncSetAttribute(edge_ws_kernel,
                             cudaFuncAttributeMaxDynamicSharedMemorySize, SMEM_TOTAL);
    }

    w_convert_kernel<<<(H * 384 + 255) / 256, 256>>>(W);
    const int nf4 = N * DN / 4;
    nf_convert_kernel<<<(nf4 + 255) / 256, 256>>>(nf, nf4);
    const int gf4 = G * DG / 4;
    gf_convert_kernel<<<(gf4 + 255) / 256, 256>>>(gf, gf4);
    edge_ws_kernel<<<sms, THREADS, SMEM_TOTAL>>>(ef, ei, batch, out, E, ntiles);
}